// round 2
// baseline (speedup 1.0000x reference)
#include <cuda_runtime.h>

// Lag2Eul CIC deposit: x (2,4,128,128,128) f32 -> out (2,1,128,128,128) f32
// DIS_NORM = 6*512/1000 = 3.072

#define DIM   128
#define PNUM  (128*128*128)      // 2097152
#define NB    2
#define DISN  3.072f

__device__ float g_sum[6];       // per-(n,c) channel sums, c < 3

__global__ void zero_accum_kernel() {
    if (threadIdx.x < 6) g_sum[threadIdx.x] = 0.0f;
}

// blockIdx.y in [0,6): n = y/3, c = y%3. Grid-stride sum over P elements.
__global__ void reduce_mean_kernel(const float* __restrict__ x) {
    int y = blockIdx.y;
    int n = y / 3, c = y % 3;
    const float* base = x + ((size_t)n * 4 + c) * PNUM;

    float s = 0.0f;
    for (int i = blockIdx.x * blockDim.x + threadIdx.x; i < PNUM;
         i += gridDim.x * blockDim.x)
        s += base[i];

    // warp reduce
    #pragma unroll
    for (int o = 16; o > 0; o >>= 1)
        s += __shfl_down_sync(0xffffffffu, s, o);

    __shared__ float ws[8];
    if ((threadIdx.x & 31) == 0) ws[threadIdx.x >> 5] = s;
    __syncthreads();
    if (threadIdx.x < 8) {
        s = ws[threadIdx.x];
        #pragma unroll
        for (int o = 4; o > 0; o >>= 1)
            s += __shfl_down_sync(0xffu, s, o);
        if (threadIdx.x == 0) atomicAdd(&g_sum[y], s);
    }
}

__global__ void scatter_kernel(const float* __restrict__ x,
                               float* __restrict__ out) {
    int p = blockIdx.x * blockDim.x + threadIdx.x;
    int n = blockIdx.y;
    if (p >= PNUM) return;

    const float invP = 1.0f / (float)PNUM;
    const float* xb = x + (size_t)n * 4 * PNUM;
    float m0 = g_sum[n * 3 + 0] * invP;
    float m1 = g_sum[n * 3 + 1] * invP;
    float m2 = g_sum[n * 3 + 2] * invP;

    int w = p & 127;
    int h = (p >> 7) & 127;
    int d = p >> 14;

    float p0 = (xb[p]            - m0) * DISN + (float)d + 0.5f;
    float p1 = (xb[PNUM + p]     - m1) * DISN + (float)h + 0.5f;
    float p2 = (xb[2 * PNUM + p] - m2) * DISN + (float)w + 0.5f;
    float v  =  xb[3 * PNUM + p];

    float i0 = floorf(p0), i1 = floorf(p1), i2 = floorf(p2);
    float f0 = p0 - i0, f1 = p1 - i1, f2 = p2 - i2;
    int t0 = (int)i0, t1 = (int)i1, t2 = (int)i2;

    float* ob = out + (size_t)n * PNUM;

    #pragma unroll
    for (int nn = 0; nn < 8; nn++) {
        int a0 = t0 + (nn & 1);
        int a1 = t1 + ((nn >> 1) & 1);
        int a2 = t2 + ((nn >> 2) & 1);
        float wt = ((nn & 1)        ? f0 : 1.0f - f0)
                 * (((nn >> 1) & 1) ? f1 : 1.0f - f1)
                 * (((nn >> 2) & 1) ? f2 : 1.0f - f2);
        if ((unsigned)a0 < 128u && (unsigned)a1 < 128u && (unsigned)a2 < 128u)
            atomicAdd(&ob[(a0 << 14) + (a1 << 7) + a2], v * wt);
    }
}

extern "C" void kernel_launch(void* const* d_in, const int* in_sizes, int n_in,
                              void* d_out, int out_size) {
    const float* x = (const float*)d_in[0];
    float* out = (float*)d_out;

    cudaMemsetAsync(out, 0, (size_t)out_size * sizeof(float));

    zero_accum_kernel<<<1, 32>>>();

    dim3 rgrid(256, 6);
    reduce_mean_kernel<<<rgrid, 256>>>(x);

    dim3 sgrid((PNUM + 255) / 256, NB);
    scatter_kernel<<<sgrid, 256>>>(x, out);
}

// round 3
// speedup vs baseline: 1.0104x; 1.0104x over previous
#include <cuda_runtime.h>

// Lag2Eul CIC deposit: x (2,4,128,128,128) f32 -> out (2,1,128,128,128) f32
// DIS_NORM = 6*512/1000 = 3.072

#define DIM   128
#define PNUM  (128*128*128)      // 2097152
#define NB    2
#define DISN  3.072f

__device__ float g_sum[6];       // per-(n,c) channel sums, c < 3

__global__ void zero_accum_kernel() {
    if (threadIdx.x < 6) g_sum[threadIdx.x] = 0.0f;
}

// blockIdx.y in [0,6): n = y/3, c = y%3. Grid-stride sum over P elements.
__global__ void reduce_mean_kernel(const float* __restrict__ x) {
    int y = blockIdx.y;
    int n = y / 3, c = y % 3;
    const float* base = x + ((size_t)n * 4 + c) * PNUM;

    float s = 0.0f;
    for (int i = blockIdx.x * blockDim.x + threadIdx.x; i < PNUM;
         i += gridDim.x * blockDim.x)
        s += base[i];

    // warp reduce
    #pragma unroll
    for (int o = 16; o > 0; o >>= 1)
        s += __shfl_down_sync(0xffffffffu, s, o);

    __shared__ float ws[8];
    if ((threadIdx.x & 31) == 0) ws[threadIdx.x >> 5] = s;
    __syncthreads();
    if (threadIdx.x < 8) {
        s = ws[threadIdx.x];
        #pragma unroll
        for (int o = 4; o > 0; o >>= 1)
            s += __shfl_down_sync(0xffu, s, o);
        if (threadIdx.x == 0) atomicAdd(&g_sum[y], s);
    }
}

__global__ void scatter_kernel(const float* __restrict__ x,
                               float* __restrict__ out) {
    int p = blockIdx.x * blockDim.x + threadIdx.x;
    int n = blockIdx.y;
    if (p >= PNUM) return;

    const float invP = 1.0f / (float)PNUM;
    const float* xb = x + (size_t)n * 4 * PNUM;
    float m0 = g_sum[n * 3 + 0] * invP;
    float m1 = g_sum[n * 3 + 1] * invP;
    float m2 = g_sum[n * 3 + 2] * invP;

    int w = p & 127;
    int h = (p >> 7) & 127;
    int d = p >> 14;

    float p0 = (xb[p]            - m0) * DISN + (float)d + 0.5f;
    float p1 = (xb[PNUM + p]     - m1) * DISN + (float)h + 0.5f;
    float p2 = (xb[2 * PNUM + p] - m2) * DISN + (float)w + 0.5f;
    float v  =  xb[3 * PNUM + p];

    float i0 = floorf(p0), i1 = floorf(p1), i2 = floorf(p2);
    float f0 = p0 - i0, f1 = p1 - i1, f2 = p2 - i2;
    int t0 = (int)i0, t1 = (int)i1, t2 = (int)i2;

    float* ob = out + (size_t)n * PNUM;

    #pragma unroll
    for (int nn = 0; nn < 8; nn++) {
        int a0 = t0 + (nn & 1);
        int a1 = t1 + ((nn >> 1) & 1);
        int a2 = t2 + ((nn >> 2) & 1);
        float wt = ((nn & 1)        ? f0 : 1.0f - f0)
                 * (((nn >> 1) & 1) ? f1 : 1.0f - f1)
                 * (((nn >> 2) & 1) ? f2 : 1.0f - f2);
        if ((unsigned)a0 < 128u && (unsigned)a1 < 128u && (unsigned)a2 < 128u)
            atomicAdd(&ob[(a0 << 14) + (a1 << 7) + a2], v * wt);
    }
}

extern "C" void kernel_launch(void* const* d_in, const int* in_sizes, int n_in,
                              void* d_out, int out_size) {
    const float* x = (const float*)d_in[0];
    float* out = (float*)d_out;

    cudaMemsetAsync(out, 0, (size_t)out_size * sizeof(float));

    zero_accum_kernel<<<1, 32>>>();

    dim3 rgrid(256, 6);
    reduce_mean_kernel<<<rgrid, 256>>>(x);

    dim3 sgrid((PNUM + 255) / 256, NB);
    scatter_kernel<<<sgrid, 256>>>(x, out);
}

// round 4
// speedup vs baseline: 1.2416x; 1.2289x over previous
#include <cuda_runtime.h>

// Lag2Eul CIC deposit: x (2,4,128,128,128) f32 -> out (2,1,128,128,128) f32
// DIS_NORM = 6*512/1000 = 3.072

#define DIM   128
#define PNUM  (128*128*128)      // 2097152
#define NB    2
#define DISN  3.072f

__device__ float g_sum[6];       // per-(n,c) channel sums, c < 3

__global__ void zero_accum_kernel() {
    if (threadIdx.x < 6) g_sum[threadIdx.x] = 0.0f;
}

// blockIdx.y in [0,6): n = y/3, c = y%3. Grid-stride float4 sum over P elements.
__global__ void reduce_mean_kernel(const float* __restrict__ x) {
    int y = blockIdx.y;
    int n = y / 3, c = y % 3;
    const float4* base = (const float4*)(x + ((size_t)n * 4 + c) * PNUM);
    const int P4 = PNUM / 4;

    float s = 0.0f;
    for (int i = blockIdx.x * blockDim.x + threadIdx.x; i < P4;
         i += gridDim.x * blockDim.x) {
        float4 v = base[i];
        s += (v.x + v.y) + (v.z + v.w);
    }

    #pragma unroll
    for (int o = 16; o > 0; o >>= 1)
        s += __shfl_down_sync(0xffffffffu, s, o);

    __shared__ float ws[8];
    if ((threadIdx.x & 31) == 0) ws[threadIdx.x >> 5] = s;
    __syncthreads();
    if (threadIdx.x < 8) {
        s = ws[threadIdx.x];
        #pragma unroll
        for (int o = 4; o > 0; o >>= 1)
            s += __shfl_down_sync(0xffu, s, o);
        if (threadIdx.x == 0) atomicAdd(&g_sum[y], s);
    }
}

// 8 lanes per particle. Lane-corner bit layout (within the 8-lane group):
//   bit0 -> w offset (adjacent addresses on adjacent lanes => sector merge)
//   bit1 -> h offset, bit2 -> d offset
// One warp-wide RED.ADD.F32 covers 4 particles x 8 corners; the w-pairs
// coalesce into a single 32B-sector wavefront 7/8 of the time.
__global__ void __launch_bounds__(256)
scatter_kernel(const float* __restrict__ x, float* __restrict__ out) {
    int t = blockIdx.x * blockDim.x + threadIdx.x;   // particle*8 + corner
    int p = t >> 3;
    int corner = t & 7;
    int n = blockIdx.y;

    const float invP = 1.0f / (float)PNUM;
    const float* xb = x + (size_t)n * 4 * PNUM;
    float m0 = g_sum[n * 3 + 0] * invP;
    float m1 = g_sum[n * 3 + 1] * invP;
    float m2 = g_sum[n * 3 + 2] * invP;

    int w = p & 127;
    int h = (p >> 7) & 127;
    int d = p >> 14;

    // 8 lanes load the same 4 addresses -> warp-broadcast, coalesced.
    float p0 = (__ldg(xb + p)            - m0) * DISN + (float)d + 0.5f;
    float p1 = (__ldg(xb + PNUM + p)     - m1) * DISN + (float)h + 0.5f;
    float p2 = (__ldg(xb + 2 * PNUM + p) - m2) * DISN + (float)w + 0.5f;
    float v  =  __ldg(xb + 3 * PNUM + p);

    float i0 = floorf(p0), i1 = floorf(p1), i2 = floorf(p2);
    float f0 = p0 - i0, f1 = p1 - i1, f2 = p2 - i2;
    int t0 = (int)i0, t1 = (int)i1, t2 = (int)i2;

    int cw = corner & 1;
    int ch = (corner >> 1) & 1;
    int cd = (corner >> 2) & 1;

    int a0 = t0 + cd;
    int a1 = t1 + ch;
    int a2 = t2 + cw;

    float wt = (cd ? f0 : 1.0f - f0)
             * (ch ? f1 : 1.0f - f1)
             * (cw ? f2 : 1.0f - f2);

    if (((unsigned)a0 < 128u) & ((unsigned)a1 < 128u) & ((unsigned)a2 < 128u)) {
        float* ob = out + (size_t)n * PNUM;
        atomicAdd(&ob[(a0 << 14) + (a1 << 7) + a2], v * wt);
    }
}

extern "C" void kernel_launch(void* const* d_in, const int* in_sizes, int n_in,
                              void* d_out, int out_size) {
    const float* x = (const float*)d_in[0];
    float* out = (float*)d_out;

    cudaMemsetAsync(out, 0, (size_t)out_size * sizeof(float));

    zero_accum_kernel<<<1, 32>>>();

    dim3 rgrid(256, 6);
    reduce_mean_kernel<<<rgrid, 256>>>(x);

    // 8 threads per particle
    dim3 sgrid((PNUM * 8) / 256, NB);
    scatter_kernel<<<sgrid, 256>>>(x, out);
}